// round 13
// baseline (speedup 1.0000x reference)
#include <cuda_runtime.h>
#include <cuda_bf16.h>
#include <stdint.h>
#include <math.h>

// Problem constants
#define B_      32
#define CIN     512
#define HW      4096          // 64*64
#define VD      16
#define NCHUNK1 8             // pixel chunks per image in k_root (512 px each)
#define NCHUNK3 8             // chunks per image in k_mant (512 px each)
#define NST     5             // cp.async pipeline depth
#define CPS     4             // channels per stage
#define NSTAGES (CIN / CPS)   // 128 stage iterations

typedef unsigned long long ull;

// Scratch (device globals; no allocation allowed)
__device__ float g_feats0[B_ * VD * HW];          // 8 MB, layout [b][k][pixel]
__device__ float g_pool_part[B_ * NCHUNK1 * VD];  // per-chunk pooled partial sums
__device__ float g_M[B_ * VD * VD];               // composed path matrix per batch
__device__ float g_cvec[B_ * VD];                 // composed path bias per batch
__device__ float g_mpart[B_ * NCHUNK3];           // mantissa partial sums
__device__ int   g_ctr_root;                      // k_root completion counter
__device__ int   g_ctr_mant;                      // k_mant completion counter

__constant__ int c_off[4] = {0, 2, 5, 9};         // LEVEL_OFFSETS

// ---- f32x2 packed helpers (Blackwell FFMA2, PTX-only) ----------------------
__device__ __forceinline__ ull pack2(float lo, float hi) {
    ull r;
    asm("mov.b64 %0, {%1, %2};" : "=l"(r) : "f"(lo), "f"(hi));
    return r;
}
__device__ __forceinline__ void fma2(ull& d, ull a, ull b) {
    asm("fma.rn.f32x2 %0, %1, %2, %0;" : "+l"(d) : "l"(a), "l"(b));
}
__device__ __forceinline__ ull mul2(ull a, ull b) {
    ull r;
    asm("mul.rn.f32x2 %0, %1, %2;" : "=l"(r) : "l"(a), "l"(b));
    return r;
}
__device__ __forceinline__ void unpack2(ull p, float& lo, float& hi) {
    asm("mov.b64 {%0, %1}, %2;" : "=f"(lo), "=f"(hi) : "l"(p));
}
__device__ __forceinline__ void cp_async16(unsigned int saddr, const void* gptr) {
    asm volatile("cp.async.cg.shared.global [%0], [%1], 16;"
                 :: "r"(saddr), "l"(gptr) : "memory");
}

// ---------------------------------------------------------------------------
// Binomial tree on pooled vectors, adapted to a 128-thread block.
// ---------------------------------------------------------------------------
__device__ void tree_body128(const float* __restrict__ lw,
                             const float* __restrict__ lb,
                             float* __restrict__ out, int tid)
{
    __shared__ float P[5][VD], Pn[5][VD];
    __shared__ float norms[5];
    __shared__ int   choice[5][5];
    __shared__ int   path[5];
    __shared__ float M[256], cv[VD];

    for (int b = 0; b < B_; b++) {
        if (tid < VD) {
            float s = 0.f;
#pragma unroll
            for (int c = 0; c < NCHUNK1; c++)
                s += g_pool_part[(b * NCHUNK1 + c) * VD + tid];
            P[0][tid] = s * (1.0f / (float)HW);
        }
        __syncthreads();

        int ncur = 1;
        for (int level = 1; level <= 4; level++) {
            const int off = c_off[level - 1];
            const int nn  = level + 1;
            if (tid < ncur) {
                float s = 0.f;
#pragma unroll
                for (int k = 0; k < VD; k++) s += P[tid][k] * P[tid][k];
                norms[tid] = sqrtf(s);
            }
            __syncthreads();
            if (tid < nn) {
                int pl = tid - 1; if (pl < 0) pl = 0;
                int pr = tid;     if (pr > level - 1) pr = level - 1;
                int ch = pl;
                if (pl != pr && norms[pr] > norms[pl]) ch = pr;
                choice[level][tid] = ch;
            }
            __syncthreads();
            if (tid < nn * VD) {          // nn*VD <= 80 < 128
                int node = tid >> 4, i = tid & 15;
                const float* W = lw + (size_t)(off + node) * VD * VD + i * VD;
                const float* par = P[choice[level][node]];
                float s = lb[(off + node) * VD + i];
#pragma unroll
                for (int k = 0; k < VD; k++) s = fmaf(W[k], par[k], s);
                Pn[node][i] = s;
            }
            __syncthreads();
            if (tid < nn * VD) P[tid >> 4][tid & 15] = Pn[tid >> 4][tid & 15];
            __syncthreads();
            ncur = nn;
        }

        if (tid < 5) {
            float s = 0.f;
#pragma unroll
            for (int k = 0; k < VD; k++) s += P[tid][k] * P[tid][k];
            norms[tid] = sqrtf(s);
            out[b * 5 + tid] = norms[tid];  // class_logits
        }
        __syncthreads();
        if (tid == 0) {
            int best = 0; float bv = norms[0];
            for (int j = 1; j < 5; j++)
                if (norms[j] > bv) { bv = norms[j]; best = j; }
            out[192 + b] = (float)best;     // selected_class
            path[4] = best;
            path[3] = choice[4][path[4]];
            path[2] = choice[3][path[3]];
            path[1] = choice[2][path[2]];
        }
        __syncthreads();

        // Compose path matrix/bias; each of 128 threads handles 2 entries
        {
            int idx0 = c_off[0] + path[1];
#pragma unroll
            for (int q = 0; q < 2; q++) {
                int e = tid + q * 128, i = e >> 4, j = e & 15;
                M[e] = lw[(size_t)idx0 * 256 + i * 16 + j];
                if (j == 0) cv[i] = lb[idx0 * 16 + i];
            }
        }
        __syncthreads();
        for (int l = 2; l <= 4; l++) {
            int idx = c_off[l - 1] + path[l];
            const float* W = lw + (size_t)idx * 256;
            float sv[2], scv[2];
#pragma unroll
            for (int q = 0; q < 2; q++) {
                int e = tid + q * 128, i = e >> 4, j = e & 15;
                float s = 0.f;
#pragma unroll
                for (int k = 0; k < 16; k++)
                    s = fmaf(W[i * 16 + k], M[k * 16 + j], s);
                sv[q] = s;
                if (j == 0) {
                    float sc = lb[idx * 16 + i];
#pragma unroll
                    for (int k = 0; k < 16; k++)
                        sc = fmaf(W[i * 16 + k], cv[k], sc);
                    scv[q] = sc;
                }
            }
            __syncthreads();
#pragma unroll
            for (int q = 0; q < 2; q++) {
                int e = tid + q * 128, i = e >> 4, j = e & 15;
                M[e] = sv[q];
                if (j == 0) cv[i] = scv[q];
            }
            __syncthreads();
        }
#pragma unroll
        for (int q = 0; q < 2; q++) {
            int e = tid + q * 128;
            g_M[b * 256 + e] = M[e];
            if ((e & 15) == 0) g_cvec[b * VD + (e >> 4)] = cv[e >> 4];
        }
        __syncthreads();
    }
}

// ---------------------------------------------------------------------------
// Kernel 1: feats0 = root_w @ features + root_b, pooled partials, fused tree.
// grid (NCHUNK1, B_) = 256 blocks x 128 threads (R11 pipeline, proven).
// Weights DUP-PACKED in smem (64 KB): inner loop = 4 w-LDS.128 + 2 x-LDS.128
// + 32 FFMA2, zero broadcast movs. In-block transpose is conflict-aware:
// lane's k determines bank (2k distinct across 16 lanes, 2-way for g).
// smem: 64KB ws2 + NST*8KB stages = 104KB -> 2 blocks/SM.
// ---------------------------------------------------------------------------
__global__ __launch_bounds__(128, 2)
void k_root(const float* __restrict__ feat,
            const float* __restrict__ rw,   // (16, 512)
            const float* __restrict__ rb,   // (16,)
            const float* __restrict__ lw,   // (14,16,16)
            const float* __restrict__ lb,   // (14,16)
            float* __restrict__ out)
{
    extern __shared__ float smem_dyn[];
    float* ws2 = smem_dyn;                  // 512 rows x 32 floats = 64 KB
    float* stg = smem_dyn + CIN * 32;       // NST stages of 4*512 floats

    const int t     = threadIdx.x;
    const int chunk = blockIdx.x;
    const int b     = blockIdx.y;
    const int kg    = t >> 6;               // 0 or 1 (k-half)
    const int lane  = t & 63;               // pixel lane (8 consecutive px)

    const float* gbase = feat + (size_t)b * CIN * HW + chunk * 512;

    // Prologue: start the cp.async pipeline immediately (stages 0..NST-2)
    unsigned int stg_s = (unsigned int)__cvta_generic_to_shared(stg);
#pragma unroll
    for (int s = 0; s < NST - 1; s++) {
        const float* g = gbase + (size_t)(s * CPS) * HW + t * 4;
        unsigned int d = stg_s + (unsigned int)(s) * (CPS * 512 * 4) + t * 16;
#pragma unroll
        for (int j = 0; j < CPS; j++)
            cp_async16(d + j * 2048, g + (size_t)j * HW);
        asm volatile("cp.async.commit_group;" ::: "memory");
    }

    // Dup-packed weight staging: thread (k = t&15, g = t>>4) streams 64
    // consecutive c of row k; STS.64 banks = 2k (distinct across lanes).
    {
        const int kk = t & 15, gg = t >> 4;
        const float* src = rw + (size_t)kk * CIN + gg * 64;
        float* dst = ws2 + (size_t)(gg * 64) * 32 + 2 * kk;
        for (int c = 0; c < 64; c++) {
            float w = __ldg(&src[c]);
            *reinterpret_cast<float2*>(dst + c * 32) = make_float2(w, w);
        }
    }

    // Accumulators: 8 k-outputs x 4 pixel-pairs, initialized with bias
    ull acc[8][4];
#pragma unroll
    for (int k = 0; k < 8; k++) {
        float bk = __ldg(&rb[kg * 8 + k]);
        ull bp = pack2(bk, bk);
#pragma unroll
        for (int pp = 0; pp < 4; pp++) acc[k][pp] = bp;
    }
    __syncthreads();   // ws2 visible to all warps

    // Main pipeline loop over 128 stages of 4 channels
    for (int cs = 0; cs < NSTAGES; cs++) {
        asm volatile("cp.async.wait_group %0;" :: "n"(NST - 2) : "memory");
        __syncthreads();

        const int slot = cs % NST;
        const float* sb = stg + slot * (CPS * 512);
        const int cbase = cs * CPS;
#pragma unroll
        for (int j = 0; j < CPS; j++) {
            const ulonglong2* wr = reinterpret_cast<const ulonglong2*>(
                ws2 + (size_t)(cbase + j) * 32 + kg * 16);
            ulonglong2 w01 = wr[0], w23 = wr[1];
            ulonglong2 w45 = wr[2], w67 = wr[3];
            ull wp[8] = {w01.x, w01.y, w23.x, w23.y,
                         w45.x, w45.y, w67.x, w67.y};

            const ulonglong2* xp = reinterpret_cast<const ulonglong2*>(
                sb + j * 512 + lane * 8);
            ulonglong2 xa = xp[0], xb = xp[1];
            ull xv[4] = {xa.x, xa.y, xb.x, xb.y};
#pragma unroll
            for (int k = 0; k < 8; k++) {
#pragma unroll
                for (int pp = 0; pp < 4; pp++)
                    fma2(acc[k][pp], wp[k], xv[pp]);
            }
        }
        __syncthreads();

        int ns = cs + NST - 1;
        if (ns < NSTAGES) {
            const float* g = gbase + (size_t)(ns * CPS) * HW + t * 4;
            unsigned int d = stg_s
                + (unsigned int)(ns % NST) * (CPS * 512 * 4) + t * 16;
#pragma unroll
            for (int j = 0; j < CPS; j++)
                cp_async16(d + j * 2048, g + (size_t)j * HW);
        }
        asm volatile("cp.async.commit_group;" ::: "memory");
    }

    // Epilogue: store feats0 + pooled partials
    float* ob = g_feats0 + (size_t)b * VD * HW + chunk * 512 + lane * 8;
    float ps[8];
#pragma unroll
    for (int k = 0; k < 8; k++) {
        float v0, v1, v2, v3, v4, v5, v6, v7;
        unpack2(acc[k][0], v0, v1);
        unpack2(acc[k][1], v2, v3);
        unpack2(acc[k][2], v4, v5);
        unpack2(acc[k][3], v6, v7);
        float* o = ob + (size_t)(kg * 8 + k) * HW;
        *reinterpret_cast<float4*>(o)     = make_float4(v0, v1, v2, v3);
        *reinterpret_cast<float4*>(o + 4) = make_float4(v4, v5, v6, v7);
        ps[k] = ((v0 + v1) + (v2 + v3)) + ((v4 + v5) + (v6 + v7));
    }

#pragma unroll
    for (int off = 16; off > 0; off >>= 1) {
#pragma unroll
        for (int k = 0; k < 8; k++)
            ps[k] += __shfl_xor_sync(0xffffffffu, ps[k], off);
    }
    __shared__ float wpool[4][8];
    const int wid = t >> 5, lid = t & 31;
    if (lid == 0) {
#pragma unroll
        for (int k = 0; k < 8; k++) wpool[wid][k] = ps[k];
    }
    __syncthreads();
    if (t < 16) {
        int kh = t >> 3, k = t & 7;
        float s = wpool[kh * 2][k] + wpool[kh * 2 + 1][k];
        g_pool_part[(b * NCHUNK1 + chunk) * VD + kh * 8 + k] = s;
    }

    // Last-finishing block runs the pooled binomial tree (deterministic)
    __shared__ int is_last;
    __syncthreads();
    if (t == 0) {
        __threadfence();
        int v = atomicAdd(&g_ctr_root, 1);
        is_last = (v == (int)(gridDim.x * gridDim.y) - 1);
    }
    __syncthreads();
    if (is_last) {
        tree_body128(lw, lb, out, t);
        if (t == 0) g_ctr_root = 0;
    }
}

// ---------------------------------------------------------------------------
// Kernel 2: selected feature -> normalize -> MLP(64) -> scalar mean.
// f32x2-packed: each thread processes a PIXEL PAIR in packed registers; Ms and
// w1 dup-packed in smem. Fused finalization in last block.
// grid: (NCHUNK3, B_), block: 256.
// ---------------------------------------------------------------------------
__global__ __launch_bounds__(256)
void k_mant(const float* __restrict__ m1w,  // (64,16)
            const float* __restrict__ m1b,  // (64,)
            const float* __restrict__ m2w,  // (1,64)
            const float* __restrict__ m2b,  // (1,)
            float* __restrict__ out)
{
    __shared__ ull  Ms2[256];               // dup-packed path matrix (2 KB)
    __shared__ ull  w12[64 * VD];           // dup-packed m1w (8 KB)
    __shared__ float cs[VD], b1[64], w2[64];
    __shared__ int is_last;
    const int tid   = threadIdx.x;
    const int chunk = blockIdx.x;
    const int b     = blockIdx.y;

    {
        float m = g_M[b * 256 + tid];
        Ms2[tid] = pack2(m, m);
    }
    if (tid < VD) cs[tid] = g_cvec[b * VD + tid];
    for (int idx = tid; idx < 64 * VD; idx += 256) {
        float w = m1w[idx];
        w12[idx] = pack2(w, w);
    }
    if (tid < 64) { b1[tid] = m1b[tid]; w2[tid] = m2w[tid]; }
    __syncthreads();

    const int p = chunk * 512 + tid * 2;    // pixel pair
    const float* f0 = g_feats0 + (size_t)b * VD * HW + p;

    ull x2[VD];
#pragma unroll
    for (int k = 0; k < VD; k++)
        x2[k] = *reinterpret_cast<const ull*>(f0 + (size_t)k * HW);

    ull v01[VD];
#pragma unroll
    for (int i = 0; i < VD; i++) {
        ull s = pack2(cs[i], cs[i]);
#pragma unroll
        for (int k = 0; k < VD; k++) fma2(s, Ms2[i * VD + k], x2[k]);
        v01[i] = s;
    }
    ull n01 = pack2(0.f, 0.f);
#pragma unroll
    for (int i = 0; i < VD; i++) fma2(n01, v01[i], v01[i]);
    float n0, n1;
    unpack2(n01, n0, n1);
    float i0 = 1.0f / (sqrtf(n0) + 1e-8f);
    float i1 = 1.0f / (sqrtf(n1) + 1e-8f);
    ull inv01 = pack2(i0, i1);
#pragma unroll
    for (int k = 0; k < VD; k++) v01[k] = mul2(v01[k], inv01);

    float s20 = 0.f, s21 = 0.f;
#pragma unroll 4
    for (int jj = 0; jj < 64; jj++) {
        ull tt = pack2(b1[jj], b1[jj]);
#pragma unroll
        for (int k = 0; k < VD; k++) fma2(tt, w12[jj * VD + k], v01[k]);
        float t0, t1;
        unpack2(tt, t0, t1);
        t0 = fmaxf(t0, 0.f);
        t1 = fmaxf(t1, 0.f);
        float w2j = w2[jj];
        s20 = fmaf(w2j, t0, s20);
        s21 = fmaf(w2j, t1, s21);
    }
    float s2 = s20 + s21;

#pragma unroll
    for (int off = 16; off > 0; off >>= 1)
        s2 += __shfl_xor_sync(0xffffffffu, s2, off);
    __shared__ float rs[8];
    int wid = tid >> 5, lane = tid & 31;
    if (lane == 0) rs[wid] = s2;
    __syncthreads();
    if (tid == 0) {
        float t = ((rs[0] + rs[1]) + (rs[2] + rs[3])) +
                  ((rs[4] + rs[5]) + (rs[6] + rs[7]));
        g_mpart[b * NCHUNK3 + chunk] = t;
    }

    // Last-block finalization (deterministic fixed-order sums)
    if (tid == 0) {
        __threadfence();
        int v2 = atomicAdd(&g_ctr_mant, 1);
        is_last = (v2 == (int)(gridDim.x * gridDim.y) - 1);
    }
    __syncthreads();
    if (is_last) {
        if (tid < B_) {
            float s = 0.f;
#pragma unroll
            for (int c = 0; c < NCHUNK3; c++) s += g_mpart[tid * NCHUNK3 + c];
            float mr = s * (1.0f / (float)HW) + m2b[0];
            float sig = 1.0f / (1.0f + expf(-mr));
            out[160 + tid] = sig * 0.75f + 0.75f;
        }
        if (tid == 0) g_ctr_mant = 0;   // reset for next graph replay
    }
}

// ---------------------------------------------------------------------------
extern "C" void kernel_launch(void* const* d_in, const int* in_sizes, int n_in,
                              void* d_out, int out_size)
{
    const float* features = (const float*)d_in[0];
    const float* root_w   = (const float*)d_in[1];
    const float* root_b   = (const float*)d_in[2];
    const float* level_w  = (const float*)d_in[3];
    const float* level_b  = (const float*)d_in[4];
    const float* m1_w     = (const float*)d_in[5];
    const float* m1_b     = (const float*)d_in[6];
    const float* m2_w     = (const float*)d_in[7];
    const float* m2_b     = (const float*)d_in[8];
    float* out = (float*)d_out;

    const int smem_root = CIN * 32 * 4 + NST * CPS * 512 * 4;  // 64KB+40KB=104KB
    cudaFuncSetAttribute(k_root, cudaFuncAttributeMaxDynamicSharedMemorySize,
                         smem_root);

    dim3 g1(NCHUNK1, B_);
    k_root<<<g1, 128, smem_root>>>(features, root_w, root_b,
                                   level_w, level_b, out);

    dim3 g3(NCHUNK3, B_);
    k_mant<<<g3, 256>>>(m1_w, m1_b, m2_w, m2_b, out);
}

// round 15
// speedup vs baseline: 2.1739x; 2.1739x over previous
#include <cuda_runtime.h>
#include <cuda_bf16.h>
#include <stdint.h>
#include <math.h>

// Problem constants
#define B_      32
#define CIN     512
#define HW      4096          // 64*64
#define VD      16
#define NCHUNK1 8             // pixel chunks per image in k_root (512 px each)
#define NCHUNK3 4             // chunks per image in k_mant (1024 px each)
#define NST     6             // cp.async pipeline depth
#define CPS     4             // channels per stage
#define NSTAGES (CIN / CPS)   // 128 stage iterations

typedef unsigned long long ull;

// Scratch (device globals; no allocation allowed)
__device__ float g_feats0[B_ * VD * HW];          // 8 MB, layout [b][k][pixel]
__device__ float g_pool_part[B_ * NCHUNK1 * VD];  // per-chunk pooled partials
__device__ float g_M[B_ * VD * VD];               // composed path matrix per batch
__device__ float g_cvec[B_ * VD];                 // composed path bias per batch
__device__ float g_mpart[B_ * NCHUNK3];           // mantissa partial sums
__device__ int   g_ctr_mant;                      // k_mant completion counter

__constant__ int c_off[4] = {0, 2, 5, 9};         // LEVEL_OFFSETS

// ---- f32x2 packed helpers (Blackwell FFMA2, PTX-only) ----------------------
__device__ __forceinline__ ull pack2(float lo, float hi) {
    ull r;
    asm("mov.b64 %0, {%1, %2};" : "=l"(r) : "f"(lo), "f"(hi));
    return r;
}
__device__ __forceinline__ void fma2(ull& d, ull a, ull b) {
    asm("fma.rn.f32x2 %0, %1, %2, %0;" : "+l"(d) : "l"(a), "l"(b));
}
__device__ __forceinline__ ull mul2(ull a, ull b) {
    ull r;
    asm("mul.rn.f32x2 %0, %1, %2;" : "=l"(r) : "l"(a), "l"(b));
    return r;
}
__device__ __forceinline__ void unpack2(ull p, float& lo, float& hi) {
    asm("mov.b64 {%0, %1}, %2;" : "=f"(lo), "=f"(hi) : "l"(p));
}
__device__ __forceinline__ void cp_async16(unsigned int saddr, const void* gptr) {
    asm volatile("cp.async.cg.shared.global [%0], [%1], 16;"
                 :: "r"(saddr), "l"(gptr) : "memory");
}

// ---------------------------------------------------------------------------
// Kernel 1: feats0 = root_w @ features + root_b, plus pooled partial sums.
// (R11 configuration — best measured, 76.8us.)  grid (NCHUNK1, B_), 128 thr.
// ---------------------------------------------------------------------------
__global__ __launch_bounds__(128, 2)
void k_root(const float* __restrict__ feat,
            const float* __restrict__ rw,   // (16, 512)
            const float* __restrict__ rb)   // (16,)
{
    extern __shared__ float smem_dyn[];
    float* ws   = smem_dyn;                 // 512*16 floats = 32 KB
    float* stg  = smem_dyn + CIN * VD;      // NST stages of 4*512 floats

    const int t     = threadIdx.x;
    const int chunk = blockIdx.x;
    const int b     = blockIdx.y;
    const int kg    = t >> 6;               // 0 or 1 (k-half)
    const int lane  = t & 63;               // pixel lane

    const float* gbase = feat + (size_t)b * CIN * HW + chunk * 512;

    unsigned int stg_s = (unsigned int)__cvta_generic_to_shared(stg);
#pragma unroll
    for (int s = 0; s < NST - 1; s++) {
        const float* g = gbase + (size_t)(s * CPS) * HW + t * 4;
        unsigned int d = stg_s + (unsigned int)(s) * (CPS * 512 * 4) + t * 16;
#pragma unroll
        for (int j = 0; j < CPS; j++)
            cp_async16(d + j * 2048, g + (size_t)j * HW);
        asm volatile("cp.async.commit_group;" ::: "memory");
    }

    for (int i = t; i < CIN * VD; i += 128) {
        int c = i >> 4, k = i & 15;
        ws[i] = rw[k * CIN + c];
    }

    ull acc[8][4];
#pragma unroll
    for (int k = 0; k < 8; k++) {
        float bk = __ldg(&rb[kg * 8 + k]);
        ull bp = pack2(bk, bk);
#pragma unroll
        for (int pp = 0; pp < 4; pp++) acc[k][pp] = bp;
    }

    for (int cs = 0; cs < NSTAGES; cs++) {
        asm volatile("cp.async.wait_group %0;" :: "n"(NST - 2) : "memory");
        __syncthreads();

        const int slot = cs % NST;
        const float* sb = stg + slot * (CPS * 512);
        const int cbase = cs * CPS;
#pragma unroll
        for (int j = 0; j < CPS; j++) {
            const float* wrow = ws + (cbase + j) * VD + kg * 8;
            float4 wa = *reinterpret_cast<const float4*>(wrow);
            float4 wb = *reinterpret_cast<const float4*>(wrow + 4);
            ull wp[8];
            wp[0] = pack2(wa.x, wa.x); wp[1] = pack2(wa.y, wa.y);
            wp[2] = pack2(wa.z, wa.z); wp[3] = pack2(wa.w, wa.w);
            wp[4] = pack2(wb.x, wb.x); wp[5] = pack2(wb.y, wb.y);
            wp[6] = pack2(wb.z, wb.z); wp[7] = pack2(wb.w, wb.w);

            const ull* xp = reinterpret_cast<const ull*>(sb + j * 512 + lane * 8);
            ull x0 = xp[0], x1 = xp[1], x2 = xp[2], x3 = xp[3];
#pragma unroll
            for (int k = 0; k < 8; k++) {
                fma2(acc[k][0], wp[k], x0);
                fma2(acc[k][1], wp[k], x1);
                fma2(acc[k][2], wp[k], x2);
                fma2(acc[k][3], wp[k], x3);
            }
        }
        __syncthreads();

        int ns = cs + NST - 1;
        if (ns < NSTAGES) {
            const float* g = gbase + (size_t)(ns * CPS) * HW + t * 4;
            unsigned int d = stg_s
                + (unsigned int)(ns % NST) * (CPS * 512 * 4) + t * 16;
#pragma unroll
            for (int j = 0; j < CPS; j++)
                cp_async16(d + j * 2048, g + (size_t)j * HW);
        }
        asm volatile("cp.async.commit_group;" ::: "memory");
    }

    float* ob = g_feats0 + (size_t)b * VD * HW + chunk * 512 + lane * 8;
    float ps[8];
#pragma unroll
    for (int k = 0; k < 8; k++) {
        float v0, v1, v2, v3, v4, v5, v6, v7;
        unpack2(acc[k][0], v0, v1);
        unpack2(acc[k][1], v2, v3);
        unpack2(acc[k][2], v4, v5);
        unpack2(acc[k][3], v6, v7);
        float* o = ob + (size_t)(kg * 8 + k) * HW;
        *reinterpret_cast<float4*>(o)     = make_float4(v0, v1, v2, v3);
        *reinterpret_cast<float4*>(o + 4) = make_float4(v4, v5, v6, v7);
        ps[k] = ((v0 + v1) + (v2 + v3)) + ((v4 + v5) + (v6 + v7));
    }

#pragma unroll
    for (int off = 16; off > 0; off >>= 1) {
#pragma unroll
        for (int k = 0; k < 8; k++)
            ps[k] += __shfl_xor_sync(0xffffffffu, ps[k], off);
    }
    __shared__ float wpool[4][8];
    const int wid = t >> 5, lid = t & 31;
    if (lid == 0) {
#pragma unroll
        for (int k = 0; k < 8; k++) wpool[wid][k] = ps[k];
    }
    __syncthreads();
    if (t < 16) {
        int kh = t >> 3, k = t & 7;
        float s = wpool[kh * 2][k] + wpool[kh * 2 + 1][k];
        g_pool_part[(b * NCHUNK1 + chunk) * VD + kh * 8 + k] = s;
    }
}

// ---------------------------------------------------------------------------
// Kernel 2: pooled binomial tree per batch (verbatim). grid: B_, block: 256
// ---------------------------------------------------------------------------
__global__ __launch_bounds__(256)
void k_tree(const float* __restrict__ lw,   // (14,16,16)
            const float* __restrict__ lb,   // (14,16)
            float* __restrict__ out)
{
    const int b   = blockIdx.x;
    const int tid = threadIdx.x;

    __shared__ float P[5][VD], Pn[5][VD];
    __shared__ float norms[5];
    __shared__ int   choice[5][5];
    __shared__ int   path[5];
    __shared__ float M[VD * VD], cv[VD];

    if (tid < VD) {
        float s = 0.f;
#pragma unroll
        for (int c = 0; c < NCHUNK1; c++)
            s += g_pool_part[(b * NCHUNK1 + c) * VD + tid];
        P[0][tid] = s * (1.0f / (float)HW);
    }
    __syncthreads();

    int ncur = 1;
    for (int level = 1; level <= 4; level++) {
        const int off = c_off[level - 1];
        const int nn  = level + 1;
        if (tid < ncur) {
            float s = 0.f;
#pragma unroll
            for (int k = 0; k < VD; k++) s += P[tid][k] * P[tid][k];
            norms[tid] = sqrtf(s);
        }
        __syncthreads();
        if (tid < nn) {
            int pl = tid - 1; if (pl < 0) pl = 0;
            int pr = tid;     if (pr > level - 1) pr = level - 1;
            int ch = pl;
            if (pl != pr && norms[pr] > norms[pl]) ch = pr;
            choice[level][tid] = ch;
        }
        __syncthreads();
        if (tid < nn * VD) {
            int node = tid >> 4, i = tid & 15;
            const float* W = lw + (size_t)(off + node) * VD * VD + i * VD;
            const float* par = P[choice[level][node]];
            float s = lb[(off + node) * VD + i];
#pragma unroll
            for (int k = 0; k < VD; k++) s = fmaf(W[k], par[k], s);
            Pn[node][i] = s;
        }
        __syncthreads();
        if (tid < nn * VD) P[tid >> 4][tid & 15] = Pn[tid >> 4][tid & 15];
        __syncthreads();
        ncur = nn;
    }

    if (tid < 5) {
        float s = 0.f;
#pragma unroll
        for (int k = 0; k < VD; k++) s += P[tid][k] * P[tid][k];
        norms[tid] = sqrtf(s);
        out[b * 5 + tid] = norms[tid];          // class_logits
    }
    __syncthreads();
    if (tid == 0) {
        int best = 0; float bv = norms[0];
        for (int j = 1; j < 5; j++)
            if (norms[j] > bv) { bv = norms[j]; best = j; }
        out[192 + b] = (float)best;             // selected_class
        path[4] = best;
        path[3] = choice[4][path[4]];
        path[2] = choice[3][path[3]];
        path[1] = choice[2][path[2]];
    }
    __syncthreads();

    const int i = tid >> 4, j = tid & 15;
    {
        int idx = c_off[0] + path[1];
        M[tid] = lw[(size_t)idx * 256 + i * 16 + j];
        if (j == 0) cv[i] = lb[idx * 16 + i];
    }
    __syncthreads();
    for (int l = 2; l <= 4; l++) {
        int idx = c_off[l - 1] + path[l];
        const float* W = lw + (size_t)idx * 256;
        float s = 0.f;
#pragma unroll
        for (int k = 0; k < 16; k++) s = fmaf(W[i * 16 + k], M[k * 16 + j], s);
        float sc = 0.f;
        if (j == 0) {
            sc = lb[idx * 16 + i];
#pragma unroll
            for (int k = 0; k < 16; k++) sc = fmaf(W[i * 16 + k], cv[k], sc);
        }
        __syncthreads();
        M[tid] = s;
        if (j == 0) cv[i] = sc;
        __syncthreads();
    }
    g_M[b * 256 + tid] = M[tid];
    if (j == 0) g_cvec[b * VD + i] = cv[i];
}

// ---------------------------------------------------------------------------
// Kernel 3: selected feature -> normalize -> MLP(64) -> scalar mean.
// FOUR pixels per thread as 2 packed f32x2 pairs; Ms and w1 dup-packed in
// smem, read via ulonglong2 (LDS.128). Fused finalization in last block.
// grid: (NCHUNK3, B_) = 128 blocks, block: 256.
// ---------------------------------------------------------------------------
__global__ __launch_bounds__(256)
void k_mant(const float* __restrict__ m1w,  // (64,16)
            const float* __restrict__ m1b,  // (64,)
            const float* __restrict__ m2w,  // (1,64)
            const float* __restrict__ m2b,  // (1,)
            float* __restrict__ out)
{
    __shared__ ull  Ms2[256];               // dup-packed path matrix (2 KB)
    __shared__ ull  w12[64 * VD];           // dup-packed m1w (8 KB)
    __shared__ ull  b12[64];
    __shared__ ull  cs2[VD];
    __shared__ float w2s[64];
    __shared__ int is_last;
    const int tid   = threadIdx.x;
    const int chunk = blockIdx.x;
    const int b     = blockIdx.y;

    {
        float m = g_M[b * 256 + tid];
        Ms2[tid] = pack2(m, m);
    }
    for (int idx = tid; idx < 64 * VD; idx += 256) {
        float w = m1w[idx];
        w12[idx] = pack2(w, w);
    }
    if (tid < 64) {
        float bb = m1b[tid];
        b12[tid] = pack2(bb, bb);
        w2s[tid] = m2w[tid];
    }
    if (tid < VD) {
        float c = g_cvec[b * VD + tid];
        cs2[tid] = pack2(c, c);
    }
    __syncthreads();

    const ulonglong2* Ms2v = reinterpret_cast<const ulonglong2*>(Ms2);
    const ulonglong2* w12v = reinterpret_cast<const ulonglong2*>(w12);

    const int p0 = chunk * 1024 + tid * 4;  // 4 consecutive pixels
    const float* f0 = g_feats0 + (size_t)b * VD * HW + p0;

    float s2 = 0.f;
#pragma unroll
    for (int q = 0; q < 2; q++) {           // two pixel-pairs
        ull x2[VD];
#pragma unroll
        for (int k = 0; k < VD; k++)
            x2[k] = *reinterpret_cast<const ull*>(f0 + (size_t)k * HW + q * 2);

        ull v[VD];
#pragma unroll
        for (int i = 0; i < VD; i++) {
            ull s = cs2[i];
#pragma unroll
            for (int kk = 0; kk < 8; kk++) {
                ulonglong2 mm = Ms2v[i * 8 + kk];
                fma2(s, mm.x, x2[2 * kk]);
                fma2(s, mm.y, x2[2 * kk + 1]);
            }
            v[i] = s;
        }
        ull n01 = pack2(0.f, 0.f);
#pragma unroll
        for (int i = 0; i < VD; i++) fma2(n01, v[i], v[i]);
        float n0, n1;
        unpack2(n01, n0, n1);
        ull inv01 = pack2(1.0f / (sqrtf(n0) + 1e-8f),
                          1.0f / (sqrtf(n1) + 1e-8f));
#pragma unroll
        for (int k = 0; k < VD; k++) v[k] = mul2(v[k], inv01);

#pragma unroll 2
        for (int jj = 0; jj < 64; jj++) {
            ull tt = b12[jj];
#pragma unroll
            for (int kk = 0; kk < 8; kk++) {
                ulonglong2 ww = w12v[jj * 8 + kk];
                fma2(tt, ww.x, v[2 * kk]);
                fma2(tt, ww.y, v[2 * kk + 1]);
            }
            float t0, t1;
            unpack2(tt, t0, t1);
            s2 = fmaf(w2s[jj], fmaxf(t0, 0.f) + fmaxf(t1, 0.f), s2);
        }
    }

#pragma unroll
    for (int off = 16; off > 0; off >>= 1)
        s2 += __shfl_xor_sync(0xffffffffu, s2, off);
    __shared__ float rs[8];
    int wid = tid >> 5, lane = tid & 31;
    if (lane == 0) rs[wid] = s2;
    __syncthreads();
    if (tid == 0) {
        float t = ((rs[0] + rs[1]) + (rs[2] + rs[3])) +
                  ((rs[4] + rs[5]) + (rs[6] + rs[7]));
        g_mpart[b * NCHUNK3 + chunk] = t;
    }

    // Last-block finalization (deterministic fixed-order sums)
    if (tid == 0) {
        __threadfence();
        int v2 = atomicAdd(&g_ctr_mant, 1);
        is_last = (v2 == (int)(gridDim.x * gridDim.y) - 1);
    }
    __syncthreads();
    if (is_last) {
        if (tid < B_) {
            float s = 0.f;
#pragma unroll
            for (int c = 0; c < NCHUNK3; c++) s += g_mpart[tid * NCHUNK3 + c];
            float mr = s * (1.0f / (float)HW) + m2b[0];
            float sig = 1.0f / (1.0f + expf(-mr));
            out[160 + tid] = sig * 0.75f + 0.75f;
        }
        if (tid == 0) g_ctr_mant = 0;   // reset for next graph replay
    }
}

// ---------------------------------------------------------------------------
extern "C" void kernel_launch(void* const* d_in, const int* in_sizes, int n_in,
                              void* d_out, int out_size)
{
    const float* features = (const float*)d_in[0];
    const float* root_w   = (const float*)d_in[1];
    const float* root_b   = (const float*)d_in[2];
    const float* level_w  = (const float*)d_in[3];
    const float* level_b  = (const float*)d_in[4];
    const float* m1_w     = (const float*)d_in[5];
    const float* m1_b     = (const float*)d_in[6];
    const float* m2_w     = (const float*)d_in[7];
    const float* m2_b     = (const float*)d_in[8];
    float* out = (float*)d_out;

    const int smem_root = CIN * VD * 4 + NST * CPS * 512 * 4;  // 32KB + 48KB
    cudaFuncSetAttribute(k_root, cudaFuncAttributeMaxDynamicSharedMemorySize,
                         smem_root);

    dim3 g1(NCHUNK1, B_);
    k_root<<<g1, 128, smem_root>>>(features, root_w, root_b);

    k_tree<<<B_, 256>>>(level_w, level_b, out);

    dim3 g3(NCHUNK3, B_);
    k_mant<<<g3, 256>>>(m1_w, m1_b, m2_w, m2_b, out);
}